// round 7
// baseline (speedup 1.0000x reference)
#include <cuda_runtime.h>
#include <cuda_bf16.h>

// DrugBAN fused kernel, R6: fully-contiguous per-block streaming.
//
// Algebra (verified, rel_err ~2e-7): softmax rows sum to 1, so
//   drug_ctx[b,:] = (1/NT) * segment_sum(drug_x)  (rank < NMAX only)
//   tgt_ctx[b,:]  = mean_t target_h[b,t,:]
// W_a / GEMM / softmax cancel.
//
// R1..R5 all read 256B column slices strided 1KB and all pinned at
// ~5.6 TB/s. R6 tests the contiguity axis: each block reads ALL 256 dims
// of a consecutive row range (64KB contiguous streams), partials combined
// deterministically via tickets (fixed order, self-resetting).
//
// Grid (64, 20): part 0..3  = drug node-range chunks (<=128 rows each),
//                part 4..19 = target t-chunks (64 rows each).
//
// Inputs: d_in[0] drug_x f32[16384,256], d_in[1] batch_idx i32[16384] sorted,
//         d_in[2] target_h f32[64,1024,256], d_in[3] W_a (unused).
// Output: f32 [64, 512] = [drug_ctx | tgt_ctx].

#define NT_LEN   1024
#define NMAX_CAP 512
#define BATCH_B  64
#define DCHUNKS  4
#define TCHUNKS  16
#define TROWS    (NT_LEN / TCHUNKS)   // 64

__device__ float g_dpart[BATCH_B * DCHUNKS * 256];
__device__ float g_tpart[BATCH_B * TCHUNKS * 256];
__device__ int   g_dtk[BATCH_B];   // zero-init; self-resetting
__device__ int   g_ttk[BATCH_B];

__device__ __forceinline__ int lb_search(const int* __restrict__ a, int n, int key) {
    int lo = 0, hi = n;
    while (lo < hi) {
        int mid = (lo + hi) >> 1;
        if (__ldg(a + mid) < key) lo = mid + 1; else hi = mid;
    }
    return lo;
}

__device__ __forceinline__ void f4_add(float4& d, const float4 s) {
    d.x += s.x; d.y += s.y; d.z += s.z; d.w += s.w;
}

__global__ __launch_bounds__(256, 8)
void drugban_fused_kernel(const float* __restrict__ drug_x,
                          const int*   __restrict__ batch_idx,
                          const float* __restrict__ target_h,
                          float*       __restrict__ out,
                          int n_nodes) {
    const int b    = blockIdx.x;     // batch 0..63
    const int part = blockIdx.y;     // 0..3 drug chunks, 4..19 target chunks
    const int tid  = threadIdx.x;    // 256 threads
    const int col  = tid & 63;       // float4 column 0..63 (full 256-dim row)
    const int rg   = tid >> 6;       // 0..3 row group

    __shared__ float4 red[256];      // 4 KB
    __shared__ int s_ticket;

    const float scale = 1.0f / (float)NT_LEN;
    float4 acc = make_float4(0.f, 0.f, 0.f, 0.f);

    if (part < DCHUNKS) {
        // ---- drug: contiguous node-range chunk ----
        int start = lb_search(batch_idx, n_nodes, b);
        int end   = lb_search(batch_idx, n_nodes, b + 1);
        int len   = end - start;
        if (len > NMAX_CAP) len = NMAX_CAP;
        int per = (len + DCHUNKS - 1) / DCHUNKS;
        int c0 = start + part * per;
        int c1 = c0 + per; if (c1 > start + len) c1 = start + len;

        const float4* base = reinterpret_cast<const float4*>(drug_x) + col;
        #pragma unroll 2
        for (int i = c0 + rg; i < c1; i += 4)
            f4_add(acc, __ldg(base + (size_t)i * 64));

        // reduce 4 row groups (layout rg*64 + col)
        red[tid] = acc;
        __syncthreads();
        if (tid < 128) f4_add(red[tid], red[tid + 128]);
        __syncthreads();
        if (tid < 64)  f4_add(red[tid], red[tid + 64]);
        __syncthreads();

        if (tid < 64)
            reinterpret_cast<float4*>(g_dpart + (b * DCHUNKS + part) * 256)[tid] = red[tid];

        __threadfence();
        __syncthreads();
        if (tid == 0) s_ticket = atomicAdd(&g_dtk[b], 1);
        __syncthreads();

        if (s_ticket == DCHUNKS - 1) {
            __threadfence();
            if (tid < 64) {
                const float4* p = reinterpret_cast<const float4*>(g_dpart + b * DCHUNKS * 256);
                float4 r = p[tid];                       // fixed order j=0..3
                f4_add(r, p[64 + tid]);
                f4_add(r, p[128 + tid]);
                f4_add(r, p[192 + tid]);
                r.x *= scale; r.y *= scale; r.z *= scale; r.w *= scale;
                reinterpret_cast<float4*>(out + b * 512)[tid] = r;
            }
            if (tid == 0) g_dtk[b] = 0;   // reset for next graph replay
        }
    } else {
        // ---- target: contiguous 64-row t-chunk ----
        const int c = part - DCHUNKS;
        const int t0 = c * TROWS;

        const float4* base = reinterpret_cast<const float4*>(target_h)
                             + (size_t)b * (NT_LEN * 64) + col;
        #pragma unroll 4
        for (int t = t0 + rg; t < t0 + TROWS; t += 4)
            f4_add(acc, __ldg(base + (size_t)t * 64));

        red[tid] = acc;
        __syncthreads();
        if (tid < 128) f4_add(red[tid], red[tid + 128]);
        __syncthreads();
        if (tid < 64)  f4_add(red[tid], red[tid + 64]);
        __syncthreads();

        if (tid < 64)
            reinterpret_cast<float4*>(g_tpart + (b * TCHUNKS + c) * 256)[tid] = red[tid];

        __threadfence();
        __syncthreads();
        if (tid == 0) s_ticket = atomicAdd(&g_ttk[b], 1);
        __syncthreads();

        if (s_ticket == TCHUNKS - 1) {
            __threadfence();
            if (tid < 64) {
                const float4* p = reinterpret_cast<const float4*>(g_tpart + b * TCHUNKS * 256);
                float4 r = p[tid];                       // fixed order c=0..15
                #pragma unroll
                for (int j = 1; j < TCHUNKS; j++)
                    f4_add(r, p[j * 64 + tid]);
                r.x *= scale; r.y *= scale; r.z *= scale; r.w *= scale;
                reinterpret_cast<float4*>(out + b * 512 + 256)[tid] = r;
            }
            if (tid == 0) g_ttk[b] = 0;   // reset for next graph replay
        }
    }
}

extern "C" void kernel_launch(void* const* d_in, const int* in_sizes, int n_in,
                              void* d_out, int out_size) {
    const float* drug_x    = (const float*)d_in[0];
    const int*   batch_idx = (const int*)d_in[1];
    const float* target_h  = (const float*)d_in[2];
    // d_in[3] (W_a) cancels out mathematically; unused.
    float* out = (float*)d_out;
    int n_nodes = in_sizes[1];

    dim3 grid(BATCH_B, DCHUNKS + TCHUNKS);   // 64 x 20 = 1280 uniform blocks
    drugban_fused_kernel<<<grid, 256>>>(drug_x, batch_idx, target_h, out, n_nodes);
}

// round 8
// speedup vs baseline: 1.2361x; 1.2361x over previous
#include <cuda_runtime.h>
#include <cuda_bf16.h>

// DrugBAN fused kernel, R7: R1 shape (the empirical bandwidth optimum)
// + parallel segment search + explicit MLP accumulators.
//
// Algebra (verified, rel_err ~2e-7): softmax rows sum to 1, so
//   drug_ctx[b,:] = (1/NT) * segment_sum(drug_x)  (rank < NMAX only)
//   tgt_ctx[b,:]  = mean_t target_h[b,t,:]
// W_a / GEMM / softmax cancel.
//
// R2/R5/R6 falsified the occupancy / L2-hint / contiguity hypotheses; the
// R1 shape (256B slices, stride 1KB, 64x8 grid) is fastest. R7 keeps it
// and removes serial overhead only:
//  - warp0/warp1 compute start/end binary searches concurrently (was 28
//    dependent load steps, now 14) and broadcast via smem;
//  - target loop uses 4 independent accumulators (fixed combine order).
//
// Inputs: d_in[0] drug_x f32[16384,256], d_in[1] batch_idx i32[16384] sorted,
//         d_in[2] target_h f32[64,1024,256], d_in[3] W_a (unused).
// Output: f32 [64, 512] = [drug_ctx | tgt_ctx].

#define NT_LEN   1024
#define NMAX_CAP 512
#define BATCH_B  64

__device__ __forceinline__ int lb_search(const int* __restrict__ a, int n, int key) {
    int lo = 0, hi = n;
    while (lo < hi) {
        int mid = (lo + hi) >> 1;
        if (__ldg(a + mid) < key) lo = mid + 1; else hi = mid;
    }
    return lo;
}

__device__ __forceinline__ void f4_add(float4& d, const float4 s) {
    d.x += s.x; d.y += s.y; d.z += s.z; d.w += s.w;
}

__global__ __launch_bounds__(256, 8)
void drugban_fused_kernel(const float* __restrict__ drug_x,
                          const int*   __restrict__ batch_idx,
                          const float* __restrict__ target_h,
                          float*       __restrict__ out,
                          int n_nodes) {
    const int b    = blockIdx.x;     // batch 0..63
    const int part = blockIdx.y;     // 0..3 drug quarters, 4..7 target quarters
    const int tid  = threadIdx.x;    // 256 threads
    const int col  = tid & 15;       // float4 column within the 64-dim slice
    const int rg   = tid >> 4;       // 0..15 row group

    __shared__ float4 red[256];
    __shared__ int s_bounds[2];      // [start, end]

    float4 acc = make_float4(0.f, 0.f, 0.f, 0.f);

    if (part < 4) {
        // ---- parallel segment search: warp 0 -> start, warp 1 -> end ----
        if (tid == 0)  s_bounds[0] = lb_search(batch_idx, n_nodes, b);
        if (tid == 32) s_bounds[1] = lb_search(batch_idx, n_nodes, b + 1);
        __syncthreads();
        int start = s_bounds[0];
        int end   = s_bounds[1];
        if (end - start > NMAX_CAP) end = start + NMAX_CAP;  // pos>=NMAX dropped

        // ---- drug segment sum, dims [part*64, +64); row = 64 float4 ----
        const float4* base = reinterpret_cast<const float4*>(drug_x)
                             + (size_t)part * 16 + col;
        float4 a0 = acc, a1 = acc;
        int i = start + rg;
        for (; i + 16 < end; i += 32) {
            f4_add(a0, __ldg(base + (size_t)i * 64));
            f4_add(a1, __ldg(base + (size_t)(i + 16) * 64));
        }
        if (i < end) f4_add(a0, __ldg(base + (size_t)i * 64));
        acc = a0; f4_add(acc, a1);
    } else {
        // ---- target mean, dims [(part-4)*64, +64) ----
        const int q = part - 4;
        const float4* base = reinterpret_cast<const float4*>(target_h)
                             + (size_t)b * (NT_LEN * 64) + (size_t)q * 16 + col;
        // 64 iterations/thread; 4 independent accumulators for MLP
        float4 a0 = acc, a1 = acc, a2 = acc, a3 = acc;
        #pragma unroll 4
        for (int t = rg; t < NT_LEN; t += 64) {
            f4_add(a0, __ldg(base + (size_t)t * 64));
            f4_add(a1, __ldg(base + (size_t)(t + 16) * 64));
            f4_add(a2, __ldg(base + (size_t)(t + 32) * 64));
            f4_add(a3, __ldg(base + (size_t)(t + 48) * 64));
        }
        // fixed combine order -> deterministic
        f4_add(a0, a1); f4_add(a2, a3); f4_add(a0, a2);
        acc = a0;
    }

    // ---- tree-reduce 16 row groups (stride-16 layout keeps col fixed) ----
    red[tid] = acc;
    __syncthreads();
    #pragma unroll
    for (int s = 128; s >= 16; s >>= 1) {
        if (tid < s) {
            f4_add(red[tid], red[tid + s]);
        }
        __syncthreads();
    }

    if (tid < 16) {
        const float scale = 1.0f / (float)NT_LEN;  // both halves divide by NT
        float4 r = red[tid];
        r.x *= scale; r.y *= scale; r.z *= scale; r.w *= scale;
        int off = b * 512 + ((part < 4) ? part * 64 : 256 + (part - 4) * 64);
        reinterpret_cast<float4*>(out + off)[tid] = r;
    }
}

extern "C" void kernel_launch(void* const* d_in, const int* in_sizes, int n_in,
                              void* d_out, int out_size) {
    const float* drug_x    = (const float*)d_in[0];
    const int*   batch_idx = (const int*)d_in[1];
    const float* target_h  = (const float*)d_in[2];
    // d_in[3] (W_a) cancels out mathematically; unused.
    float* out = (float*)d_out;
    int n_nodes = in_sizes[1];

    dim3 grid(BATCH_B, 8);
    drugban_fused_kernel<<<grid, 256>>>(drug_x, batch_idx, target_h, out, n_nodes);
}